// round 1
// baseline (speedup 1.0000x reference)
#include <cuda_runtime.h>
#include <math.h>
#include <float.h>

#define BB 32768
#define DD 256
#define KK 4096

// ---- scratch (static device globals: allocation-free) ----
__device__ int          g_indices[BB];
__device__ float        g_wsq[KK];
__device__ unsigned int g_counts[KK];
__device__ double       g_loss;

// ---------------------------------------------------------------------------
// Kernel 0: per-codeword squared norms + zero accumulators (re-done every call,
// deterministic).
// ---------------------------------------------------------------------------
__global__ void vq_prep(const float* __restrict__ cb) {
    int k = blockIdx.x * blockDim.x + threadIdx.x;
    if (k < KK) {
        const float* w = cb + (size_t)k * DD;
        float s = 0.f;
        #pragma unroll 8
        for (int d = 0; d < DD; ++d) s += w[d] * w[d];
        g_wsq[k]    = s;
        g_counts[k] = 0u;
    }
    if (k == 0) g_loss = 0.0;
}

// ---------------------------------------------------------------------------
// Kernel 1: fused fp32 GEMM + argmin.
// Each CTA: 128 rows of z (smem-resident, transposed) x all K=4096 codewords,
// processed in 32 chunks of 128 codewords. Thread tile 8x8. Double-buffered
// codebook slices of [16 d][128 c].
// smem: zs[256][128] (128KB) + ws[2][16][128] (16KB) + zsq[128] = 147,968 B.
// ---------------------------------------------------------------------------
__global__ void __launch_bounds__(256, 1)
vq_argmin(const float* __restrict__ z, const float* __restrict__ cb) {
    extern __shared__ float sm[];
    float* zs  = sm;                    // [d][row] 256x128
    float* ws  = sm + 32768;            // [buf][dd][c] 2x16x128
    float* zsq = sm + 32768 + 4096;     // [128]

    const int tid = threadIdx.x;
    const int tx  = tid & 15;           // column group
    const int ty  = tid >> 4;           // row group
    const int row0 = blockIdx.x * 128;

    if (tid < 128) zsq[tid] = 0.f;
    __syncthreads();

    // Load z tile transposed into smem, accumulate row squared-norms.
    {
        const int r    = tid & 127;
        const int half = tid >> 7;      // 0/1: even/odd float4 columns
        const float4* zr = (const float4*)(z + (size_t)(row0 + r) * DD);
        float part = 0.f;
        #pragma unroll
        for (int j = 0; j < 32; ++j) {
            int d4 = half + j * 2;
            float4 v = zr[d4];
            int d = d4 * 4;
            zs[(d + 0) * 128 + r] = v.x;
            zs[(d + 1) * 128 + r] = v.y;
            zs[(d + 2) * 128 + r] = v.z;
            zs[(d + 3) * 128 + r] = v.w;
            part += v.x * v.x + v.y * v.y + v.z * v.z + v.w * v.w;
        }
        atomicAdd(&zsq[r], part);       // exactly 2 adds per row: deterministic
    }
    __syncthreads();

    float zsqr[8];
    #pragma unroll
    for (int i = 0; i < 8; ++i) zsqr[i] = zsq[ty * 8 + i];

    float best[8];
    int   bidx[8];
    #pragma unroll
    for (int i = 0; i < 8; ++i) { best[i] = FLT_MAX; bidx[i] = 0; }

    // Prologue: stage chunk 0, d-slice 0 into buffer 0.
    #pragma unroll
    for (int j = 0; j < 8; ++j) {
        int fi = tid + j * 256;
        int c = fi & 127, dd = fi >> 7;
        ws[dd * 128 + c] = cb[(size_t)c * DD + dd];
    }
    __syncthreads();

    int buf = 0;
    for (int ch = 0; ch < 32; ++ch) {
        float acc[8][8];
        #pragma unroll
        for (int i = 0; i < 8; ++i)
            #pragma unroll
            for (int j = 0; j < 8; ++j) acc[i][j] = 0.f;

        for (int ds = 0; ds < 16; ++ds) {
            // preload next slice (global -> regs) before compute
            int nds = ds + 1, nch = ch;
            if (nds == 16) { nds = 0; nch = ch + 1; }
            const bool hn = (nch < 32);
            float st[8];
            if (hn) {
                #pragma unroll
                for (int j = 0; j < 8; ++j) {
                    int fi = tid + j * 256;
                    int c = fi & 127, dd = fi >> 7;
                    st[j] = __ldg(&cb[(size_t)(nch * 128 + c) * DD + nds * 16 + dd]);
                }
            }

            const float* zb = zs + ds * 16 * 128 + ty * 8;
            const float* wb = ws + buf * 2048 + tx * 8;
            #pragma unroll
            for (int dd = 0; dd < 16; ++dd) {
                float zf[8], wf[8];
                *(float4*)&zf[0] = *(const float4*)(zb + dd * 128);
                *(float4*)&zf[4] = *(const float4*)(zb + dd * 128 + 4);
                *(float4*)&wf[0] = *(const float4*)(wb + dd * 128);
                *(float4*)&wf[4] = *(const float4*)(wb + dd * 128 + 4);
                #pragma unroll
                for (int i = 0; i < 8; ++i)
                    #pragma unroll
                    for (int j = 0; j < 8; ++j)
                        acc[i][j] = fmaf(zf[i], wf[j], acc[i][j]);
            }

            if (hn) {
                #pragma unroll
                for (int j = 0; j < 8; ++j) {
                    int fi = tid + j * 256;
                    int c = fi & 127, dd = fi >> 7;
                    ws[(buf ^ 1) * 2048 + dd * 128 + c] = st[j];
                }
            }
            __syncthreads();
            buf ^= 1;
        }

        // chunk epilogue: distances + running argmin (first-index tie-break:
        // strict < with ascending c keeps the earliest index)
        #pragma unroll
        for (int j = 0; j < 8; ++j) {
            int c = ch * 128 + tx * 8 + j;
            float wsqc = __ldg(&g_wsq[c]);
            #pragma unroll
            for (int i = 0; i < 8; ++i) {
                float val = (zsqr[i] + wsqc) - 2.f * acc[i][j];
                if (val < best[i]) { best[i] = val; bidx[i] = c; }
            }
        }
    }

    // reduce across the 16 column-threads sharing the same rows
    #pragma unroll
    for (int i = 0; i < 8; ++i) {
        float v = best[i]; int id = bidx[i];
        #pragma unroll
        for (int off = 8; off > 0; off >>= 1) {
            float vv = __shfl_down_sync(0xffffffffu, v, off, 16);
            int   ii = __shfl_down_sync(0xffffffffu, id, off, 16);
            if (vv < v || (vv == v && ii < id)) { v = vv; id = ii; }
        }
        if (tx == 0) g_indices[row0 + ty * 8 + i] = id;
    }
}

// ---------------------------------------------------------------------------
// Kernel 2: gather z_q -> out, squared-error partial sums, histogram,
// indices -> out (as float), zero any tail.
// ---------------------------------------------------------------------------
__global__ void vq_out(const float* __restrict__ z, const float* __restrict__ cb,
                       float* __restrict__ out, int out_size) {
    const int gid  = blockIdx.x * blockDim.x + threadIdx.x;
    const int nthr = gridDim.x * blockDim.x;

    const int nf4 = BB * (DD / 4);
    const float4* z4  = (const float4*)z;
    const float4* cb4 = (const float4*)cb;
    float4* out4 = (float4*)out;

    float lsum = 0.f;
    for (int i = gid; i < nf4; i += nthr) {
        int row = i >> 6;               // 64 float4 per row
        int d4  = i & 63;
        int idx = g_indices[row];
        float4 q = cb4[(size_t)idx * 64 + d4];
        float4 e = z4[i];
        if ((i + 1) * 4 <= out_size) out4[i] = q;
        float dx = q.x - e.x, dy = q.y - e.y, dz = q.z - e.z, dw = q.w - e.w;
        lsum += dx * dx + dy * dy + dz * dz + dw * dw;
    }

    __shared__ float red[256];
    red[threadIdx.x] = lsum;
    __syncthreads();
    for (int o = 128; o > 0; o >>= 1) {
        if (threadIdx.x < o) red[threadIdx.x] += red[threadIdx.x + o];
        __syncthreads();
    }
    if (threadIdx.x == 0) atomicAdd(&g_loss, (double)red[0]);

    if (gid < BB) {
        int idx = g_indices[gid];
        atomicAdd(&g_counts[idx], 1u);
        int pos = BB * DD + gid;
        if (pos < out_size) out[pos] = (float)idx;
    }

    // zero any unexpected tail (d_out is poisoned)
    for (int i = BB * DD + BB + 2 + gid; i < out_size; i += nthr) out[i] = 0.f;
}

// ---------------------------------------------------------------------------
// Kernel 3: finalize quant_loss and perplexity scalars.
// ---------------------------------------------------------------------------
__global__ void vq_final(float* __restrict__ out, int out_size) {
    __shared__ double red[256];
    int t = threadIdx.x;
    double s = 0.0;
    for (int k = t; k < KK; k += 256) {
        float p = (float)g_counts[k] / (float)BB;
        s += (double)(p * logf(p + 1e-10f));
    }
    red[t] = s;
    __syncthreads();
    for (int o = 128; o > 0; o >>= 1) {
        if (t < o) red[t] += red[t + o];
        __syncthreads();
    }
    if (t == 0) {
        int p0 = BB * DD + BB;
        if (p0 < out_size)
            out[p0] = (float)(g_loss / ((double)BB * (double)DD) * 1.25);
        if (p0 + 1 < out_size)
            out[p0 + 1] = expf((float)(-red[0]));
    }
}

// ---------------------------------------------------------------------------
extern "C" void kernel_launch(void* const* d_in, const int* in_sizes, int n_in,
                              void* d_out, int out_size) {
    const float* z  = (const float*)d_in[0];   // z_e [32768, 256] f32
    const float* cb = (const float*)d_in[1];   // codebook [4096, 256] f32
    float* out = (float*)d_out;

    const int smem_bytes = (32768 + 4096 + 128) * 4;  // 147,968 B
    cudaFuncSetAttribute(vq_argmin, cudaFuncAttributeMaxDynamicSharedMemorySize,
                         smem_bytes);

    vq_prep<<<(KK + 127) / 128, 128>>>(cb);
    vq_argmin<<<BB / 128, 256, smem_bytes>>>(z, cb);
    vq_out<<<256, 256>>>(z, cb, out, out_size);
    vq_final<<<1, 256>>>(out, out_size);
}

// round 3
// speedup vs baseline: 4.8134x; 4.8134x over previous
#include <cuda_runtime.h>
#include <cuda_bf16.h>
#include <math.h>
#include <float.h>
#include <stdint.h>

#define BB 32768
#define DD 256
#define KK 4096

// ---- scratch (static device globals: allocation-free) ----
__device__ int            g_indices[BB];
__device__ float          g_wsq[KK];
__device__ float          g_zsq[BB];
__device__ unsigned int   g_counts[KK];
__device__ double         g_loss;
__device__ __nv_bfloat16  g_zhi[BB * DD];
__device__ __nv_bfloat16  g_zlo[BB * DD];
__device__ __nv_bfloat16  g_whi[KK * DD];
__device__ __nv_bfloat16  g_wlo[KK * DD];

// ---------------- helpers ----------------
__device__ __forceinline__ uint32_t smem_u32(const void* p) {
    return (uint32_t)__cvta_generic_to_shared(p);
}
__device__ __forceinline__ void cp16(uint32_t dst, const void* src) {
    asm volatile("cp.async.cg.shared.global [%0], [%1], 16;" :: "r"(dst), "l"(src));
}
__device__ __forceinline__ void cp_commit() {
    asm volatile("cp.async.commit_group;" ::: "memory");
}
template <int N> __device__ __forceinline__ void cp_wait() {
    asm volatile("cp.async.wait_group %0;" :: "n"(N) : "memory");
}
__device__ __forceinline__ uint32_t swz(uint32_t off) {
    return off ^ ((off >> 3) & 0x70);
}
__device__ __forceinline__ void ldsm4(uint32_t* r, uint32_t addr) {
    asm volatile("ldmatrix.sync.aligned.m8n8.x4.shared.b16 {%0,%1,%2,%3}, [%4];"
                 : "=r"(r[0]), "=r"(r[1]), "=r"(r[2]), "=r"(r[3]) : "r"(addr));
}
__device__ __forceinline__ void mma16816(float* c, const uint32_t* a,
                                         const uint32_t* b) {
    asm volatile(
        "mma.sync.aligned.m16n8k16.row.col.f32.bf16.bf16.f32 "
        "{%0,%1,%2,%3}, {%4,%5,%6,%7}, {%8,%9}, {%0,%1,%2,%3};"
        : "+f"(c[0]), "+f"(c[1]), "+f"(c[2]), "+f"(c[3])
        : "r"(a[0]), "r"(a[1]), "r"(a[2]), "r"(a[3]), "r"(b[0]), "r"(b[1]));
}

// ---------------- smem layout (bytes) ----------------
// z hi:  4 slices x [128 rows x 64 bf16]  = 65536
// z lo:  65536
// w ring: 2 bufs x (hi 16384 + lo 16384)  = 65536
// reduction: 1024 (float[256]) + 1024 (int[256])
#define ZHI_OFF   0u
#define ZLO_OFF   65536u
#define W_OFF     131072u
#define RED_OFF   196608u
#define SMEM_BYTES 198656u

// ---------------------------------------------------------------------------
// Kernel A: split z into bf16 hi/lo, compute row norms.
// ---------------------------------------------------------------------------
__global__ void conv_z(const float* __restrict__ z) {
    int r = blockIdx.x * 8 + (threadIdx.x >> 5);
    int lane = threadIdx.x & 31;
    const float* zr = z + (size_t)r * DD;
    float s = 0.f;
    #pragma unroll
    for (int k = 0; k < 8; ++k) {
        int c = lane + k * 32;
        float x = zr[c];
        __nv_bfloat16 h = __float2bfloat16(x);
        float hf = __bfloat162float(h);
        __nv_bfloat16 l = __float2bfloat16(x - hf);
        g_zhi[(size_t)r * DD + c] = h;
        g_zlo[(size_t)r * DD + c] = l;
        s += x * x;
    }
    #pragma unroll
    for (int o = 16; o > 0; o >>= 1) s += __shfl_xor_sync(0xffffffffu, s, o);
    if (lane == 0) g_zsq[r] = s;
}

// ---------------------------------------------------------------------------
// Kernel B: split codebook into bf16 hi/lo, norms, zero accumulators.
// ---------------------------------------------------------------------------
__global__ void conv_w(const float* __restrict__ cb) {
    int r = blockIdx.x * 8 + (threadIdx.x >> 5);
    int lane = threadIdx.x & 31;
    const float* wr = cb + (size_t)r * DD;
    float s = 0.f;
    #pragma unroll
    for (int k = 0; k < 8; ++k) {
        int c = lane + k * 32;
        float x = wr[c];
        __nv_bfloat16 h = __float2bfloat16(x);
        float hf = __bfloat162float(h);
        __nv_bfloat16 l = __float2bfloat16(x - hf);
        g_whi[(size_t)r * DD + c] = h;
        g_wlo[(size_t)r * DD + c] = l;
        s += x * x;
    }
    #pragma unroll
    for (int o = 16; o > 0; o >>= 1) s += __shfl_xor_sync(0xffffffffu, s, o);
    if (lane == 0) { g_wsq[r] = s; g_counts[r] = 0u; }
    if (r == 0 && lane == 0) g_loss = 0.0;
}

// ---------------------------------------------------------------------------
// w-slice loader: slice j -> (chunk = j>>2, dslice = j&3). 128 codewords x
// 64 d, hi+lo, into ring buffer bufj. Rows of 128B, XOR-swizzled.
// ---------------------------------------------------------------------------
__device__ __forceinline__ void load_wslice(int j, int bufj, uint32_t sb, int tid) {
    const int ch = j >> 2, s = j & 3;
    const uint32_t base = sb + W_OFF + (uint32_t)bufj * 32768u;
    #pragma unroll
    for (int i = 0; i < 4; ++i) {
        int flat = i * 256 + tid;        // 1024 16B-chunks
        int n = flat >> 3, c = flat & 7;
        uint32_t off = swz((uint32_t)(n * 128 + c * 16));
        const size_t gsrc = (size_t)(ch * 128 + n) * DD + s * 64 + c * 8;
        cp16(base + off, g_whi + gsrc);
        cp16(base + 16384u + off, g_wlo + gsrc);
    }
}

// ---------------------------------------------------------------------------
// Kernel C: mma.sync bf16 split GEMM (hi*hi + hi*lo + lo*hi) + fused argmin.
// 8 warps = 4(M) x 2(N). Warp tile 32x64. D streamed in 64-wide slices.
// ---------------------------------------------------------------------------
__global__ void __launch_bounds__(256, 1)
vq_argmin_mma() {
    extern __shared__ __align__(1024) char smem[];
    const uint32_t sb = smem_u32(smem);
    const int tid = threadIdx.x;
    const int lane = tid & 31;
    const int warp = tid >> 5;
    const int wm = warp >> 1;        // 0..3 (M)
    const int wn = warp & 1;         // 0..1 (N)
    const int g = lane >> 3;
    const int l7 = lane & 7;
    const int row0 = blockIdx.x * 128;

    // ---- stage z tile (hi+lo), 4 slices of [128][64], swizzled ----
    #pragma unroll
    for (int i = 0; i < 16; ++i) {
        int flat = i * 256 + tid;            // 4096 chunks
        int s = flat >> 10;
        int rem = flat & 1023;
        int r = rem >> 3, c = rem & 7;
        uint32_t off = swz((uint32_t)(s * 16384 + r * 128 + c * 16));
        const size_t gsrc = (size_t)(row0 + r) * DD + s * 64 + c * 8;
        cp16(sb + ZHI_OFF + off, g_zhi + gsrc);
        cp16(sb + ZLO_OFF + off, g_zlo + gsrc);
    }
    cp_commit();
    load_wslice(0, 0, sb, tid); cp_commit();
    load_wslice(1, 1, sb, tid); cp_commit();

    // per-thread row norms for the 4 row-slots this thread owns
    float zsqr[4];
    #pragma unroll
    for (int slot = 0; slot < 4; ++slot) {
        int r = wm * 32 + (slot >> 1) * 16 + (slot & 1) * 8 + (lane >> 2);
        zsqr[slot] = g_zsq[row0 + r];
    }

    float best[4];
    int   bidx[4];
    #pragma unroll
    for (int i = 0; i < 4; ++i) { best[i] = FLT_MAX; bidx[i] = 0; }

    float acc[2][8][4];

    for (int idx = 0; idx < 128; ++idx) {
        const int ch = idx >> 2, s = idx & 3, buf = idx & 1;

        cp_wait<1>();
        __syncthreads();

        if (s == 0) {
            #pragma unroll
            for (int mf = 0; mf < 2; ++mf)
                #pragma unroll
                for (int nf = 0; nf < 8; ++nf)
                    #pragma unroll
                    for (int q = 0; q < 4; ++q) acc[mf][nf][q] = 0.f;
        }

        const uint32_t wbase = sb + W_OFF + (uint32_t)buf * 32768u;
        #pragma unroll
        for (int ks = 0; ks < 4; ++ks) {
            uint32_t ah[2][4], al[2][4];
            #pragma unroll
            for (int mf = 0; mf < 2; ++mf) {
                uint32_t off = (uint32_t)((wm * 32 + mf * 16 + (g & 1) * 8 + l7) * 128
                                          + ks * 32 + ((g >> 1) << 4));
                off = swz(off) + (uint32_t)(s * 16384);
                ldsm4(ah[mf], sb + ZHI_OFF + off);
                ldsm4(al[mf], sb + ZLO_OFF + off);
            }
            uint32_t bh[4][4], bl[4][4];
            #pragma unroll
            for (int p = 0; p < 4; ++p) {
                uint32_t off = (uint32_t)((wn * 64 + p * 16 + ((g >> 1) << 3) + l7) * 128
                                          + ks * 32 + ((g & 1) << 4));
                off = swz(off);
                ldsm4(bh[p], wbase + off);
                ldsm4(bl[p], wbase + 16384u + off);
            }
            #pragma unroll
            for (int mf = 0; mf < 2; ++mf)
                #pragma unroll
                for (int p = 0; p < 4; ++p) {
                    mma16816(acc[mf][2 * p],     ah[mf], &bh[p][0]);   // hi*hi
                    mma16816(acc[mf][2 * p + 1], ah[mf], &bh[p][2]);
                    mma16816(acc[mf][2 * p],     ah[mf], &bl[p][0]);   // hi*lo
                    mma16816(acc[mf][2 * p + 1], ah[mf], &bl[p][2]);
                    mma16816(acc[mf][2 * p],     al[mf], &bh[p][0]);   // lo*hi
                    mma16816(acc[mf][2 * p + 1], al[mf], &bh[p][2]);
                }
        }

        __syncthreads();
        if (idx + 2 < 128) load_wslice(idx + 2, buf, sb, tid);
        cp_commit();

        if (s == 3) {
            // fused distance + running argmin for chunk ch (cols ascending,
            // strict < keeps first index; matches reference rounding
            // fl(fl(zsq+wsq) - 2*dot))
            #pragma unroll
            for (int nf = 0; nf < 8; ++nf) {
                int col0 = ch * 128 + wn * 64 + nf * 8 + (lane & 3) * 2;
                float w0 = __ldg(&g_wsq[col0]);
                float w1 = __ldg(&g_wsq[col0 + 1]);
                #pragma unroll
                for (int mf = 0; mf < 2; ++mf) {
                    float v;
                    v = (zsqr[mf * 2] + w0) - 2.f * acc[mf][nf][0];
                    if (v < best[mf * 2]) { best[mf * 2] = v; bidx[mf * 2] = col0; }
                    v = (zsqr[mf * 2] + w1) - 2.f * acc[mf][nf][1];
                    if (v < best[mf * 2]) { best[mf * 2] = v; bidx[mf * 2] = col0 + 1; }
                    v = (zsqr[mf * 2 + 1] + w0) - 2.f * acc[mf][nf][2];
                    if (v < best[mf * 2 + 1]) { best[mf * 2 + 1] = v; bidx[mf * 2 + 1] = col0; }
                    v = (zsqr[mf * 2 + 1] + w1) - 2.f * acc[mf][nf][3];
                    if (v < best[mf * 2 + 1]) { best[mf * 2 + 1] = v; bidx[mf * 2 + 1] = col0 + 1; }
                }
            }
        }
    }

    // ---- reduce: 4 lanes per row (same lane>>2 group), then across wn ----
    float* sbest = (float*)(smem + RED_OFF);
    int*   sidx  = (int*)(smem + RED_OFF + 1024);
    #pragma unroll
    for (int slot = 0; slot < 4; ++slot) {
        float v = best[slot]; int id = bidx[slot];
        #pragma unroll
        for (int off = 1; off < 4; off <<= 1) {
            float vv = __shfl_xor_sync(0xffffffffu, v, off);
            int   ii = __shfl_xor_sync(0xffffffffu, id, off);
            if (vv < v || (vv == v && ii < id)) { v = vv; id = ii; }
        }
        if ((lane & 3) == 0) {
            int r = wm * 32 + (slot >> 1) * 16 + (slot & 1) * 8 + (lane >> 2);
            sbest[wn * 128 + r] = v;
            sidx[wn * 128 + r] = id;
        }
    }
    __syncthreads();
    if (tid < 128) {
        float v0 = sbest[tid], v1 = sbest[128 + tid];
        int i0 = sidx[tid], i1 = sidx[128 + tid];
        g_indices[row0 + tid] = (v1 < v0 || (v1 == v0 && i1 < i0)) ? i1 : i0;
    }
}

// ---------------------------------------------------------------------------
// Kernel D: gather z_q -> out, squared-error partials, histogram, indices.
// ---------------------------------------------------------------------------
__global__ void vq_out(const float* __restrict__ z, const float* __restrict__ cb,
                       float* __restrict__ out, int out_size) {
    const int gid  = blockIdx.x * blockDim.x + threadIdx.x;
    const int nthr = gridDim.x * blockDim.x;

    const int nf4 = BB * (DD / 4);
    const float4* z4  = (const float4*)z;
    const float4* cb4 = (const float4*)cb;
    float4* out4 = (float4*)out;

    float lsum = 0.f;
    for (int i = gid; i < nf4; i += nthr) {
        int row = i >> 6;
        int d4  = i & 63;
        int idx = g_indices[row];
        float4 q = cb4[(size_t)idx * 64 + d4];
        float4 e = z4[i];
        if ((i + 1) * 4 <= out_size) out4[i] = q;
        float dx = q.x - e.x, dy = q.y - e.y, dz = q.z - e.z, dw = q.w - e.w;
        lsum += dx * dx + dy * dy + dz * dz + dw * dw;
    }

    __shared__ float red[256];
    red[threadIdx.x] = lsum;
    __syncthreads();
    for (int o = 128; o > 0; o >>= 1) {
        if (threadIdx.x < o) red[threadIdx.x] += red[threadIdx.x + o];
        __syncthreads();
    }
    if (threadIdx.x == 0) atomicAdd(&g_loss, (double)red[0]);

    if (gid < BB) {
        int idx = g_indices[gid];
        atomicAdd(&g_counts[idx], 1u);
        int pos = BB * DD + gid;
        if (pos < out_size) out[pos] = (float)idx;
    }

    for (int i = BB * DD + BB + 2 + gid; i < out_size; i += nthr) out[i] = 0.f;
}

// ---------------------------------------------------------------------------
// Kernel E: finalize scalars.
// ---------------------------------------------------------------------------
__global__ void vq_final(float* __restrict__ out, int out_size) {
    __shared__ double red[256];
    int t = threadIdx.x;
    double s = 0.0;
    for (int k = t; k < KK; k += 256) {
        float p = (float)g_counts[k] / (float)BB;
        s += (double)(p * logf(p + 1e-10f));
    }
    red[t] = s;
    __syncthreads();
    for (int o = 128; o > 0; o >>= 1) {
        if (t < o) red[t] += red[t + o];
        __syncthreads();
    }
    if (t == 0) {
        int p0 = BB * DD + BB;
        if (p0 < out_size)
            out[p0] = (float)(g_loss / ((double)BB * (double)DD) * 1.25);
        if (p0 + 1 < out_size)
            out[p0 + 1] = expf((float)(-red[0]));
    }
}

// ---------------------------------------------------------------------------
extern "C" void kernel_launch(void* const* d_in, const int* in_sizes, int n_in,
                              void* d_out, int out_size) {
    const float* z  = (const float*)d_in[0];   // z_e [32768, 256] f32
    const float* cb = (const float*)d_in[1];   // codebook [4096, 256] f32
    float* out = (float*)d_out;

    cudaFuncSetAttribute(vq_argmin_mma,
                         cudaFuncAttributeMaxDynamicSharedMemorySize, SMEM_BYTES);

    conv_z<<<BB / 8, 256>>>(z);
    conv_w<<<KK / 8, 256>>>(cb);
    vq_argmin_mma<<<BB / 128, 256, SMEM_BYTES>>>();
    vq_out<<<512, 256>>>(z, cb, out, out_size);
    vq_final<<<1, 256>>>(out, out_size);
}

// round 4
// speedup vs baseline: 9.2735x; 1.9266x over previous
#include <cuda_runtime.h>
#include <cuda_bf16.h>
#include <math.h>
#include <float.h>
#include <stdint.h>

#define BB 32768
#define DD 256
#define KK 4096

// ---- scratch (static device globals: allocation-free) ----
__device__ float          g_wsq[KK];
__device__ unsigned int   g_counts[KK];
__device__ double         g_loss;
__device__ __nv_bfloat16  g_whi[KK * DD];
__device__ float          g_cval[BB * 16];   // per-row 16-candidate pool (dot)
__device__ int            g_cidx[BB * 16];

// ---------------- helpers ----------------
__device__ __forceinline__ uint32_t smem_u32(const void* p) {
    return (uint32_t)__cvta_generic_to_shared(p);
}
__device__ __forceinline__ void cp16(uint32_t dst, const void* src) {
    asm volatile("cp.async.cg.shared.global [%0], [%1], 16;" :: "r"(dst), "l"(src));
}
__device__ __forceinline__ void cp_commit() {
    asm volatile("cp.async.commit_group;" ::: "memory");
}
template <int N> __device__ __forceinline__ void cp_wait() {
    asm volatile("cp.async.wait_group %0;" :: "n"(N) : "memory");
}
__device__ __forceinline__ uint32_t swz(uint32_t off) {
    return off ^ ((off >> 3) & 0x70);
}
__device__ __forceinline__ void ldsm4(uint32_t* r, uint32_t addr) {
    asm volatile("ldmatrix.sync.aligned.m8n8.x4.shared.b16 {%0,%1,%2,%3}, [%4];"
                 : "=r"(r[0]), "=r"(r[1]), "=r"(r[2]), "=r"(r[3]) : "r"(addr));
}
__device__ __forceinline__ void mma16816(float* c, const uint32_t* a,
                                         const uint32_t* b) {
    asm volatile(
        "mma.sync.aligned.m16n8k16.row.col.f32.bf16.bf16.f32 "
        "{%0,%1,%2,%3}, {%4,%5,%6,%7}, {%8,%9}, {%0,%1,%2,%3};"
        : "+f"(c[0]), "+f"(c[1]), "+f"(c[2]), "+f"(c[3])
        : "r"(a[0]), "r"(a[1]), "r"(a[2]), "r"(a[3]), "r"(b[0]), "r"(b[1]));
}

// ---------------- pass-1 smem layout (bytes) ----------------
// z hi: 4 slices x [128 rows x 64 bf16] = 65536 ; w ring: 2 x 16384 = 32768
#define ZH_OFF    0u
#define W_OFF     65536u
#define SMEM_BYTES 98304u

// ---------------------------------------------------------------------------
// Kernel A: codebook -> bf16 hi, norms, zero accumulators.
// ---------------------------------------------------------------------------
__global__ void conv_w(const float* __restrict__ cb) {
    int r = blockIdx.x * 8 + (threadIdx.x >> 5);
    int lane = threadIdx.x & 31;
    const float* wr = cb + (size_t)r * DD;
    float s = 0.f;
    #pragma unroll
    for (int k = 0; k < 8; ++k) {
        int c = lane + k * 32;
        float x = wr[c];
        g_whi[(size_t)r * DD + c] = __float2bfloat16(x);
        s += x * x;
    }
    #pragma unroll
    for (int o = 16; o > 0; o >>= 1) s += __shfl_xor_sync(0xffffffffu, s, o);
    if (lane == 0) { g_wsq[r] = s; g_counts[r] = 0u; }
    if (r == 0 && lane == 0) g_loss = 0.0;
}

// ---------------------------------------------------------------------------
// w-slice loader: slice j = (chunk j>>2, dslice j&3): 128 codes x 64 dims (hi).
// ---------------------------------------------------------------------------
__device__ __forceinline__ void load_wslice(int j, int bufj, uint32_t sb, int tid) {
    const int ch = j >> 2, s = j & 3;
    const uint32_t base = sb + W_OFF + (uint32_t)bufj * 16384u;
    #pragma unroll
    for (int i = 0; i < 4; ++i) {
        int flat = i * 256 + tid;        // 1024 16B-chunks
        int n = flat >> 3, c = flat & 7;
        uint32_t off = swz((uint32_t)(n * 128 + c * 16));
        cp16(base + off, g_whi + (size_t)(ch * 128 + n) * DD + s * 64 + c * 8);
    }
}

// ---------------------------------------------------------------------------
// Pass 1: single-product bf16 GEMM; per-thread top-2 (by dot) candidate pool.
// 8 warps = 4(M) x 2(N), warp tile 32x64, 2 CTAs/SM.
// ---------------------------------------------------------------------------
__global__ void __launch_bounds__(256, 2)
vq_pass1(const float* __restrict__ z) {
    extern __shared__ __align__(1024) char smem[];
    const uint32_t sb = smem_u32(smem);
    const int tid = threadIdx.x;
    const int lane = tid & 31;
    const int warp = tid >> 5;
    const int wm = warp >> 1;        // 0..3 (M)
    const int wn = warp & 1;         // 0..1 (N)
    const int g = lane >> 3;
    const int l7 = lane & 7;
    const int row0 = blockIdx.x * 128;

    // prefetch w slices 0,1 (cp.async groups 1 and 2)
    load_wslice(0, 0, sb, tid); cp_commit();
    load_wslice(1, 1, sb, tid); cp_commit();

    // ---- stage z fp32 -> bf16 hi into smem (fused conversion) ----
    #pragma unroll
    for (int i = 0; i < 32; ++i) {
        int flat = i * 256 + tid;            // 8192 float4
        int r = flat >> 6, d4 = flat & 63;
        float4 v = *(const float4*)(z + (size_t)(row0 + r) * DD + d4 * 4);
        __nv_bfloat162 p0 = __float22bfloat162_rn(make_float2(v.x, v.y));
        __nv_bfloat162 p1 = __float22bfloat162_rn(make_float2(v.z, v.w));
        uint2 pk;
        pk.x = *(uint32_t*)&p0; pk.y = *(uint32_t*)&p1;
        uint32_t off = swz((uint32_t)((d4 >> 4) * 16384 + r * 128 + (d4 & 15) * 8));
        *(uint2*)(smem + ZH_OFF + off) = pk;
    }

    float b0v[4], b1v[4];
    int   b0i[4], b1i[4];
    #pragma unroll
    for (int i = 0; i < 4; ++i) {
        b0v[i] = -FLT_MAX; b1v[i] = -FLT_MAX; b0i[i] = 0; b1i[i] = 0;
    }

    float acc[2][8][4];

    for (int idx = 0; idx < 128; ++idx) {
        const int ch = idx >> 2, s = idx & 3, buf = idx & 1;

        cp_wait<1>();
        __syncthreads();

        if (s == 0) {
            #pragma unroll
            for (int mf = 0; mf < 2; ++mf)
                #pragma unroll
                for (int nf = 0; nf < 8; ++nf)
                    #pragma unroll
                    for (int q = 0; q < 4; ++q) acc[mf][nf][q] = 0.f;
        }

        const uint32_t wbase = sb + W_OFF + (uint32_t)buf * 16384u;
        #pragma unroll
        for (int ks = 0; ks < 4; ++ks) {
            uint32_t ah[2][4];
            #pragma unroll
            for (int mf = 0; mf < 2; ++mf) {
                uint32_t off = (uint32_t)((wm * 32 + mf * 16 + (g & 1) * 8 + l7) * 128
                                          + ks * 32 + ((g >> 1) << 4));
                ldsm4(ah[mf], sb + ZH_OFF + swz(off) + (uint32_t)(s * 16384));
            }
            uint32_t bh[4][4];
            #pragma unroll
            for (int p = 0; p < 4; ++p) {
                uint32_t off = (uint32_t)((wn * 64 + p * 16 + ((g >> 1) << 3) + l7) * 128
                                          + ks * 32 + ((g & 1) << 4));
                ldsm4(bh[p], wbase + swz(off));
            }
            #pragma unroll
            for (int mf = 0; mf < 2; ++mf)
                #pragma unroll
                for (int p = 0; p < 4; ++p) {
                    mma16816(acc[mf][2 * p],     ah[mf], &bh[p][0]);
                    mma16816(acc[mf][2 * p + 1], ah[mf], &bh[p][2]);
                }
        }

        __syncthreads();
        if (idx + 2 < 128) load_wslice(idx + 2, buf, sb, tid);
        cp_commit();

        if (s == 3) {
            // track per-(thread,row-slot) top-2 by dot (bigger = closer)
            #pragma unroll
            for (int nf = 0; nf < 8; ++nf) {
                int col0 = ch * 128 + wn * 64 + nf * 8 + (lane & 3) * 2;
                #pragma unroll
                for (int mf = 0; mf < 2; ++mf) {
                    #pragma unroll
                    for (int q = 0; q < 4; ++q) {
                        int sl = mf * 2 + (q >> 1);
                        float v = acc[mf][nf][q];
                        int c = col0 + (q & 1);
                        if (v > b1v[sl]) {
                            if (v > b0v[sl]) {
                                b1v[sl] = b0v[sl]; b1i[sl] = b0i[sl];
                                b0v[sl] = v;       b0i[sl] = c;
                            } else { b1v[sl] = v; b1i[sl] = c; }
                        }
                    }
                }
            }
        }
    }

    // write 2 candidates per (thread, row-slot) -> 16 per row
    #pragma unroll
    for (int sl = 0; sl < 4; ++sl) {
        int r = row0 + (sl >> 1 == 0 ? 0 : 16);   // placeholder, computed below
        r = row0 + (warp >> 1) * 32 + (sl >> 1) * 16 + (sl & 1) * 8 + (lane >> 2);
        int base = r * 16 + wn * 8 + (lane & 3) * 2;
        g_cval[base] = b0v[sl];     g_cidx[base] = b0i[sl];
        g_cval[base + 1] = b1v[sl]; g_cidx[base + 1] = b1i[sl];
    }
}

// ---------------------------------------------------------------------------
// Pass 2 (fused output): per row select top-4 candidates, exact fp32 rescore
// with reference rounding fl(fl(zsq+wsq) - 2*dot) + first-index tie-break,
// then write z_q, index, histogram, loss partials. One warp per row.
// ---------------------------------------------------------------------------
__global__ void __launch_bounds__(256)
vq_rescore(const float* __restrict__ z, const float* __restrict__ cb,
           float* __restrict__ out, int out_size) {
    const int lane = threadIdx.x & 31;
    const int row = blockIdx.x * 8 + (threadIdx.x >> 5);

    // z row: 8 dims per lane
    float zr[8];
    {
        float4 a = *(const float4*)(z + (size_t)row * DD + lane * 8);
        float4 b = *(const float4*)(z + (size_t)row * DD + lane * 8 + 4);
        zr[0] = a.x; zr[1] = a.y; zr[2] = a.z; zr[3] = a.w;
        zr[4] = b.x; zr[5] = b.y; zr[6] = b.z; zr[7] = b.w;
    }
    float zsq = 0.f;
    #pragma unroll
    for (int k = 0; k < 8; ++k) zsq += zr[k] * zr[k];
    #pragma unroll
    for (int o = 16; o > 0; o >>= 1) zsq += __shfl_xor_sync(0xffffffffu, zsq, o);

    // candidate pool
    float cv = -FLT_MAX; int ci = 0x7fffffff;
    if (lane < 16) { cv = g_cval[row * 16 + lane]; ci = g_cidx[row * 16 + lane]; }

    int cand[4];
    #pragma unroll
    for (int t = 0; t < 4; ++t) {
        float m = cv; int mi = ci;
        #pragma unroll
        for (int o = 16; o > 0; o >>= 1) {
            float mv = __shfl_xor_sync(0xffffffffu, m, o);
            int   mj = __shfl_xor_sync(0xffffffffu, mi, o);
            if (mv > m || (mv == m && mj < mi)) { m = mv; mi = mj; }
        }
        cand[t] = mi;
        if (ci == mi) cv = -FLT_MAX;
    }

    // exact fp32 rescore of 4 candidates
    float wreg[4][8];
    float dist[4];
    #pragma unroll
    for (int t = 0; t < 4; ++t) {
        const float* wp = cb + (size_t)cand[t] * DD + lane * 8;
        float4 a = *(const float4*)wp;
        float4 b = *(const float4*)(wp + 4);
        wreg[t][0] = a.x; wreg[t][1] = a.y; wreg[t][2] = a.z; wreg[t][3] = a.w;
        wreg[t][4] = b.x; wreg[t][5] = b.y; wreg[t][6] = b.z; wreg[t][7] = b.w;
        float d = 0.f;
        #pragma unroll
        for (int k = 0; k < 8; ++k) d = fmaf(zr[k], wreg[t][k], d);
        #pragma unroll
        for (int o = 16; o > 0; o >>= 1) d += __shfl_xor_sync(0xffffffffu, d, o);
        // reference rounding: fl(fl(zsq + wsq) - 2*dot)
        dist[t] = (zsq + __ldg(&g_wsq[cand[t]])) - 2.f * d;
    }
    int wt = 0;
    #pragma unroll
    for (int t = 1; t < 4; ++t)
        if (dist[t] < dist[wt] || (dist[t] == dist[wt] && cand[t] < cand[wt]))
            wt = t;
    const int widx = cand[wt];

    // outputs
    float lsum = 0.f;
    {
        float o0[4], o1[4];
        #pragma unroll
        for (int k = 0; k < 4; ++k) { o0[k] = wreg[wt][k]; o1[k] = wreg[wt][k + 4]; }
        float* op = out + (size_t)row * DD + lane * 8;
        if ((row + 1) * DD <= out_size) {
            *(float4*)op = make_float4(o0[0], o0[1], o0[2], o0[3]);
            *(float4*)(op + 4) = make_float4(o1[0], o1[1], o1[2], o1[3]);
        }
        #pragma unroll
        for (int k = 0; k < 8; ++k) {
            float d = wreg[wt][k] - zr[k];
            lsum += d * d;
        }
    }
    #pragma unroll
    for (int o = 16; o > 0; o >>= 1) lsum += __shfl_xor_sync(0xffffffffu, lsum, o);

    if (lane == 0) {
        atomicAdd(&g_counts[widx], 1u);
        atomicAdd(&g_loss, (double)lsum);
        int pos = BB * DD + row;
        if (pos < out_size) out[pos] = (float)widx;
    }
}

// ---------------------------------------------------------------------------
// Finalize scalars.
// ---------------------------------------------------------------------------
__global__ void vq_final(float* __restrict__ out, int out_size) {
    __shared__ double red[32];
    int t = threadIdx.x;
    double s = 0.0;
    for (int k = t; k < KK; k += 1024) {
        float p = (float)g_counts[k] / (float)BB;
        s += (double)(p * logf(p + 1e-10f));
    }
    #pragma unroll
    for (int o = 16; o > 0; o >>= 1) s += __shfl_xor_sync(0xffffffffu, s, o);
    if ((t & 31) == 0) red[t >> 5] = s;
    __syncthreads();
    if (t < 32) {
        double v = (t < 32) ? red[t] : 0.0;
        #pragma unroll
        for (int o = 16; o > 0; o >>= 1) v += __shfl_xor_sync(0xffffffffu, v, o);
        if (t == 0) {
            int p0 = BB * DD + BB;
            if (p0 < out_size)
                out[p0] = (float)(g_loss / ((double)BB * (double)DD) * 1.25);
            if (p0 + 1 < out_size)
                out[p0 + 1] = expf((float)(-v));
        }
    }
}

// ---------------------------------------------------------------------------
extern "C" void kernel_launch(void* const* d_in, const int* in_sizes, int n_in,
                              void* d_out, int out_size) {
    const float* z  = (const float*)d_in[0];   // z_e [32768, 256] f32
    const float* cb = (const float*)d_in[1];   // codebook [4096, 256] f32
    float* out = (float*)d_out;

    cudaFuncSetAttribute(vq_pass1,
                         cudaFuncAttributeMaxDynamicSharedMemorySize, SMEM_BYTES);

    conv_w<<<KK / 8, 256>>>(cb);
    vq_pass1<<<BB / 128, 256, SMEM_BYTES>>>(z);
    vq_rescore<<<BB / 8, 256>>>(z, cb, out, out_size);
    vq_final<<<1, 1024>>>(out, out_size);
}